// round 1
// baseline (speedup 1.0000x reference)
#include <cuda_runtime.h>

// Problem constants (fixed by setup_inputs)
#define B_    32
#define NIN   512
#define DIN   64
#define NOUT  32
#define DOUT  64
#define MD    2048            // NOUT*DOUT
#define NCHUNK 32             // n per routing block
#define NBLK  (NIN / NCHUNK)  // 16

// Output layout (concatenated, reference return order)
#define OFS_NCV 0
#define OFS_ACT (B_ * NOUT * DOUT)                 // 65536
#define OFS_QK  (OFS_ACT + B_ * NOUT)              // 66560
#define OFS_EMB (OFS_QK + B_ * NIN * NOUT)         // 590848

// Scratch (device globals; allocation-free rule)
__device__ float g_votes[(size_t)B_ * NIN * MD];   // 134 MB
__device__ float g_ncv0[B_ * MD];
__device__ float g_ncv1[B_ * MD];

// ---------------------------------------------------------------------------
// Votes: votes[b,n,m,d] = sum_a pose[b,n,a] * W[n,a,m,d]
// Block = (n, 256-column chunk of m*64+d). 256 threads; each thread owns one
// column and all 32 batches as 16 packed f32x2 accumulators.
// ---------------------------------------------------------------------------
__global__ __launch_bounds__(256) void votes_kernel(
    const float* __restrict__ pose, const float* __restrict__ W)
{
    __shared__ float pose_t[DIN * B_];  // [a][b], b contiguous
    const int n   = blockIdx.x;
    const int col = blockIdx.y * 256 + threadIdx.x;

    for (int i = threadIdx.x; i < B_ * DIN; i += 256) {
        int b = i >> 6, a = i & 63;
        pose_t[a * B_ + b] = pose[((size_t)b * NIN + n) * DIN + a];
    }
    __syncthreads();

    unsigned long long acc[16];
#pragma unroll
    for (int p = 0; p < 16; p++) acc[p] = 0ull;  // bit pattern = (0.f, 0.f)

    const float* Wp = W + ((size_t)n * DIN) * MD + col;
    const ulonglong2* ps = reinterpret_cast<const ulonglong2*>(pose_t);

    for (int a = 0; a < DIN; a += 4) {
        float w[4];
#pragma unroll
        for (int u = 0; u < 4; u++) w[u] = Wp[(size_t)(a + u) * MD];
#pragma unroll
        for (int u = 0; u < 4; u++) {
            unsigned long long wp;
            asm("mov.b64 %0, {%1, %1};" : "=l"(wp) : "f"(w[u]));
#pragma unroll
            for (int j = 0; j < 8; j++) {
                ulonglong2 q = ps[(a + u) * 8 + j];  // floats 4j..4j+3 of row a+u
                asm("fma.rn.f32x2 %0, %1, %2, %0;" : "+l"(acc[2 * j])     : "l"(q.x), "l"(wp));
                asm("fma.rn.f32x2 %0, %1, %2, %0;" : "+l"(acc[2 * j + 1]) : "l"(q.y), "l"(wp));
            }
        }
    }

    float* vp = g_votes + (size_t)n * MD + col;
#pragma unroll
    for (int p = 0; p < 16; p++) {
        float lo, hi;
        asm("mov.b64 {%0, %1}, %2;" : "=f"(lo), "=f"(hi) : "l"(acc[p]));
        vp[(size_t)(2 * p)     * NIN * MD] = lo;
        vp[(size_t)(2 * p + 1) * NIN * MD] = hi;
    }
}

// ---------------------------------------------------------------------------
// ncv0[b,m,d] = sum_n votes[b,n,m,d] / NOUT
// ---------------------------------------------------------------------------
__global__ __launch_bounds__(256) void ncv0_kernel()
{
    int idx = blockIdx.x * 256 + threadIdx.x;  // 0..65535
    int b = idx >> 11, md = idx & 2047;
    const float* p = g_votes + (size_t)b * NIN * MD + md;
    float s = 0.f;
#pragma unroll 8
    for (int n = 0; n < NIN; n++) s += p[(size_t)n * MD];
    g_ncv0[idx] = s * (1.0f / NOUT);
}

// ---------------------------------------------------------------------------
// One routing iteration, fused: logits -> softmax -> weighted aggregation.
// Block = (b, chunk of 32 n). Last iteration also emits qk + route_class_emb.
// ---------------------------------------------------------------------------
template <bool LAST>
__global__ __launch_bounds__(256) void iter_kernel(
    int cur_sel, float* __restrict__ nxt_ext,
    const float* __restrict__ act,
    float* __restrict__ qk_out, float* __restrict__ emb_out)
{
    __shared__ float ncv_s[MD];
    __shared__ float tile[MD];
    __shared__ float logits_s[NOUT];
    __shared__ float qa_s[NOUT];

    const float* cur = cur_sel ? g_ncv1 : g_ncv0;
    float* nxt = LAST ? nxt_ext : (cur_sel ? g_ncv0 : g_ncv1);

    const int b = blockIdx.x;
    const int nc = blockIdx.y;
    const int t = threadIdx.x;
    const int w = t >> 5, l = t & 31;

    for (int i = t; i < MD; i += 256) ncv_s[i] = cur[b * MD + i];

    float acc[8];
#pragma unroll
    for (int k = 0; k < 8; k++) acc[k] = 0.f;

    const float* vbase = g_votes + (size_t)b * NIN * MD + (size_t)nc * NCHUNK * MD;

    for (int ni = 0; ni < NCHUNK; ni++) {
        const int n = nc * NCHUNK + ni;
        // cooperative tile load (8 KB)
        {
            const float4* s4 = reinterpret_cast<const float4*>(vbase + (size_t)ni * MD);
            float4* d4 = reinterpret_cast<float4*>(tile);
            d4[t] = s4[t];
            d4[t + 256] = s4[t + 256];
        }
        __syncthreads();

        // logits[m] = dot(tile[m,:], ncv[m,:]); warp w handles m = 4w..4w+3
#pragma unroll
        for (int q = 0; q < 4; q++) {
            int m = w * 4 + q;
            float p = tile[m * 64 + l]      * ncv_s[m * 64 + l]
                    + tile[m * 64 + 32 + l] * ncv_s[m * 64 + 32 + l];
#pragma unroll
            for (int o = 16; o > 0; o >>= 1) p += __shfl_xor_sync(0xffffffffu, p, o);
            if (l == 0) logits_s[m] = p;
        }
        __syncthreads();

        // softmax over 32 classes (warp 0), fold in activation
        if (t < 32) {
            float x = logits_s[t] * 0.125f;  // 1/sqrt(Dout)
            float mx = x;
#pragma unroll
            for (int o = 16; o > 0; o >>= 1) mx = fmaxf(mx, __shfl_xor_sync(0xffffffffu, mx, o));
            float e = __expf(x - mx);
            float s = e;
#pragma unroll
            for (int o = 16; o > 0; o >>= 1) s += __shfl_xor_sync(0xffffffffu, s, o);
            float qk = e / s;
            float av = __ldg(&act[b * NIN + n]);
            qa_s[t] = qk * av;
            if (LAST) qk_out[(size_t)(b * NIN + n) * NOUT + t] = qk;
        }
        __syncthreads();

        // weighted aggregation; last iter also writes route_class_emb
#pragma unroll
        for (int k = 0; k < 8; k++) {
            int md = t + 256 * k;
            float v = tile[md] * qa_s[md >> 6];
            acc[k] += v;
            if (LAST) emb_out[(size_t)(b * NIN + n) * MD + md] = v;
        }
        __syncthreads();  // protect tile before next overwrite
    }

#pragma unroll
    for (int k = 0; k < 8; k++) atomicAdd(&nxt[b * MD + t + 256 * k], acc[k]);
}

// ---------------------------------------------------------------------------
// next_act[b,m] = ||ncv[b,m,:]||_2  (one warp per output)
// ---------------------------------------------------------------------------
__global__ __launch_bounds__(256) void act_kernel(
    const float* __restrict__ ncv, float* __restrict__ out)
{
    int g = (blockIdx.x * 256 + threadIdx.x) >> 5;  // 0..1023
    int l = threadIdx.x & 31;
    float v0 = ncv[g * 64 + l];
    float v1 = ncv[g * 64 + 32 + l];
    float s = v0 * v0 + v1 * v1;
#pragma unroll
    for (int o = 16; o > 0; o >>= 1) s += __shfl_xor_sync(0xffffffffu, s, o);
    if (l == 0) out[g] = sqrtf(s);
}

// ---------------------------------------------------------------------------
__global__ void zero_g_kernel(int sel)
{
    float4* p = reinterpret_cast<float4*>(sel ? g_ncv1 : g_ncv0);
    int i = blockIdx.x * 256 + threadIdx.x;
    if (i < (B_ * MD) / 4) p[i] = make_float4(0.f, 0.f, 0.f, 0.f);
}

__global__ void zero_ptr_kernel(float* p)
{
    int i = blockIdx.x * 256 + threadIdx.x;
    if (i < (B_ * MD) / 4) reinterpret_cast<float4*>(p)[i] = make_float4(0.f, 0.f, 0.f, 0.f);
}

// ---------------------------------------------------------------------------
extern "C" void kernel_launch(void* const* d_in, const int* in_sizes, int n_in,
                              void* d_out, int out_size)
{
    const float* pose = (const float*)d_in[0];
    const float* act  = (const float*)d_in[1];
    const float* W    = (const float*)d_in[2];
    // d_in[3] = num_iter (== 3 in this problem; hardcoded below)

    float* out     = (float*)d_out;
    float* out_ncv = out + OFS_NCV;
    float* out_act = out + OFS_ACT;
    float* out_qk  = out + OFS_QK;
    float* out_emb = out + OFS_EMB;

    // 1) votes
    votes_kernel<<<dim3(NIN, MD / 256), 256>>>(pose, W);
    // 2) ncv0 = votes.sum(n) / Nout
    ncv0_kernel<<<(B_ * MD) / 256, 256>>>();
    // 3) iteration 1: g_ncv0 -> g_ncv1
    zero_g_kernel<<<64, 256>>>(1);
    iter_kernel<false><<<dim3(B_, NBLK), 256>>>(0, nullptr, act, nullptr, nullptr);
    // 4) iteration 2: g_ncv1 -> g_ncv0
    zero_g_kernel<<<64, 256>>>(0);
    iter_kernel<false><<<dim3(B_, NBLK), 256>>>(1, nullptr, act, nullptr, nullptr);
    // 5) iteration 3 (last): g_ncv0 -> d_out ncv; also qk + route_class_emb
    zero_ptr_kernel<<<64, 256>>>(out_ncv);
    iter_kernel<true><<<dim3(B_, NBLK), 256>>>(0, out_ncv, act, out_qk, out_emb);
    // 6) next_act = ||ncv||
    act_kernel<<<128, 256>>>(out_ncv, out_act);
}

// round 3
// speedup vs baseline: 1.0024x; 1.0024x over previous
#include <cuda_runtime.h>

// Problem constants (fixed by setup_inputs)
#define B_    32
#define NIN   512
#define DIN   64
#define NOUT  32
#define DOUT  64
#define MD    2048            // NOUT*DOUT
#define NCHUNK 32             // n per routing block
#define NBLK  (NIN / NCHUNK)  // 16

// Output layout (concatenated, reference return order)
#define OFS_NCV 0
#define OFS_ACT (B_ * NOUT * DOUT)                 // 65536
#define OFS_QK  (OFS_ACT + B_ * NOUT)              // 66560
#define OFS_EMB (OFS_QK + B_ * NIN * NOUT)         // 590848

// Scratch (device globals; allocation-free rule)
__device__ float g_votes[(size_t)B_ * NIN * MD];   // 134 MB
__device__ float g_ncv0[B_ * MD];
__device__ float g_ncv1[B_ * MD];

// ---------------------------------------------------------------------------
// Votes: votes[b,n,m,d] = sum_a pose[b,n,a] * W[n,a,m,d]
// Block = (n, 256-column chunk of m*64+d). 256 threads; each thread owns one
// column and all 32 batches as 16 packed f32x2 accumulators.
// ---------------------------------------------------------------------------
__global__ __launch_bounds__(256) void votes_kernel(
    const float* __restrict__ pose, const float* __restrict__ W)
{
    __shared__ float pose_t[DIN * B_];  // [a][b], b contiguous
    const int n   = blockIdx.x;
    const int col = blockIdx.y * 256 + threadIdx.x;

    for (int i = threadIdx.x; i < B_ * DIN; i += 256) {
        int b = i >> 6, a = i & 63;
        pose_t[a * B_ + b] = pose[((size_t)b * NIN + n) * DIN + a];
    }
    __syncthreads();

    unsigned long long acc[16];
#pragma unroll
    for (int p = 0; p < 16; p++) acc[p] = 0ull;  // bit pattern = (0.f, 0.f)

    const float* Wp = W + ((size_t)n * DIN) * MD + col;
    const ulonglong2* ps = reinterpret_cast<const ulonglong2*>(pose_t);

    for (int a = 0; a < DIN; a += 4) {
        float w[4];
#pragma unroll
        for (int u = 0; u < 4; u++) w[u] = Wp[(size_t)(a + u) * MD];
#pragma unroll
        for (int u = 0; u < 4; u++) {
            unsigned long long wp;
            asm("mov.b64 %0, {%1, %1};" : "=l"(wp) : "f"(w[u]));
#pragma unroll
            for (int j = 0; j < 8; j++) {
                ulonglong2 q = ps[(a + u) * 8 + j];  // floats 4j..4j+3 of row a+u
                asm("fma.rn.f32x2 %0, %1, %2, %0;" : "+l"(acc[2 * j])     : "l"(q.x), "l"(wp));
                asm("fma.rn.f32x2 %0, %1, %2, %0;" : "+l"(acc[2 * j + 1]) : "l"(q.y), "l"(wp));
            }
        }
    }

    float* vp = g_votes + (size_t)n * MD + col;
#pragma unroll
    for (int p = 0; p < 16; p++) {
        float lo, hi;
        asm("mov.b64 {%0, %1}, %2;" : "=f"(lo), "=f"(hi) : "l"(acc[p]));
        vp[(size_t)(2 * p)     * NIN * MD] = lo;
        vp[(size_t)(2 * p + 1) * NIN * MD] = hi;
    }
}

// ---------------------------------------------------------------------------
// ncv0[b,m,d] = sum_n votes[b,n,m,d] / NOUT
// ---------------------------------------------------------------------------
__global__ __launch_bounds__(256) void ncv0_kernel()
{
    int idx = blockIdx.x * 256 + threadIdx.x;  // 0..65535
    int b = idx >> 11, md = idx & 2047;
    const float* p = g_votes + (size_t)b * NIN * MD + md;
    float s = 0.f;
#pragma unroll 8
    for (int n = 0; n < NIN; n++) s += p[(size_t)n * MD];
    g_ncv0[idx] = s * (1.0f / NOUT);
}

// ---------------------------------------------------------------------------
// One routing iteration, fused: logits -> softmax -> weighted aggregation.
// Block = (b, chunk of 32 n). Last iteration also emits qk + route_class_emb.
// ---------------------------------------------------------------------------
template <bool LAST>
__global__ __launch_bounds__(256) void iter_kernel(
    int cur_sel, float* __restrict__ nxt_ext,
    const float* __restrict__ act,
    float* __restrict__ qk_out, float* __restrict__ emb_out)
{
    __shared__ float ncv_s[MD];
    __shared__ float tile[MD];
    __shared__ float logits_s[NOUT];
    __shared__ float qa_s[NOUT];

    const float* cur = cur_sel ? g_ncv1 : g_ncv0;
    float* nxt = LAST ? nxt_ext : (cur_sel ? g_ncv0 : g_ncv1);

    const int b = blockIdx.x;
    const int nc = blockIdx.y;
    const int t = threadIdx.x;
    const int w = t >> 5, l = t & 31;

    for (int i = t; i < MD; i += 256) ncv_s[i] = cur[b * MD + i];

    float acc[8];
#pragma unroll
    for (int k = 0; k < 8; k++) acc[k] = 0.f;

    const float* vbase = g_votes + (size_t)b * NIN * MD + (size_t)nc * NCHUNK * MD;

    for (int ni = 0; ni < NCHUNK; ni++) {
        const int n = nc * NCHUNK + ni;
        // cooperative tile load (8 KB)
        {
            const float4* s4 = reinterpret_cast<const float4*>(vbase + (size_t)ni * MD);
            float4* d4 = reinterpret_cast<float4*>(tile);
            d4[t] = s4[t];
            d4[t + 256] = s4[t + 256];
        }
        __syncthreads();

        // logits[m] = dot(tile[m,:], ncv[m,:]); warp w handles m = 4w..4w+3
#pragma unroll
        for (int q = 0; q < 4; q++) {
            int m = w * 4 + q;
            float p = tile[m * 64 + l]      * ncv_s[m * 64 + l]
                    + tile[m * 64 + 32 + l] * ncv_s[m * 64 + 32 + l];
#pragma unroll
            for (int o = 16; o > 0; o >>= 1) p += __shfl_xor_sync(0xffffffffu, p, o);
            if (l == 0) logits_s[m] = p;
        }
        __syncthreads();

        // softmax over 32 classes (warp 0), fold in activation
        if (t < 32) {
            float x = logits_s[t] * 0.125f;  // 1/sqrt(Dout)
            float mx = x;
#pragma unroll
            for (int o = 16; o > 0; o >>= 1) mx = fmaxf(mx, __shfl_xor_sync(0xffffffffu, mx, o));
            float e = __expf(x - mx);
            float s = e;
#pragma unroll
            for (int o = 16; o > 0; o >>= 1) s += __shfl_xor_sync(0xffffffffu, s, o);
            float qk = e / s;
            float av = __ldg(&act[b * NIN + n]);
            qa_s[t] = qk * av;
            if (LAST) qk_out[(size_t)(b * NIN + n) * NOUT + t] = qk;
        }
        __syncthreads();

        // weighted aggregation; last iter also writes route_class_emb
#pragma unroll
        for (int k = 0; k < 8; k++) {
            int md = t + 256 * k;
            float v = tile[md] * qa_s[md >> 6];
            acc[k] += v;
            if (LAST) emb_out[(size_t)(b * NIN + n) * MD + md] = v;
        }
        __syncthreads();  // protect tile before next overwrite
    }

#pragma unroll
    for (int k = 0; k < 8; k++) atomicAdd(&nxt[b * MD + t + 256 * k], acc[k]);
}

// ---------------------------------------------------------------------------
// next_act[b,m] = ||ncv[b,m,:]||_2  (one warp per output)
// ---------------------------------------------------------------------------
__global__ __launch_bounds__(256) void act_kernel(
    const float* __restrict__ ncv, float* __restrict__ out)
{
    int g = (blockIdx.x * 256 + threadIdx.x) >> 5;  // 0..1023
    int l = threadIdx.x & 31;
    float v0 = ncv[g * 64 + l];
    float v1 = ncv[g * 64 + 32 + l];
    float s = v0 * v0 + v1 * v1;
#pragma unroll
    for (int o = 16; o > 0; o >>= 1) s += __shfl_xor_sync(0xffffffffu, s, o);
    if (l == 0) out[g] = sqrtf(s);
}

// ---------------------------------------------------------------------------
__global__ void zero_g_kernel(int sel)
{
    float4* p = reinterpret_cast<float4*>(sel ? g_ncv1 : g_ncv0);
    int i = blockIdx.x * 256 + threadIdx.x;
    if (i < (B_ * MD) / 4) p[i] = make_float4(0.f, 0.f, 0.f, 0.f);
}

__global__ void zero_ptr_kernel(float* p)
{
    int i = blockIdx.x * 256 + threadIdx.x;
    if (i < (B_ * MD) / 4) reinterpret_cast<float4*>(p)[i] = make_float4(0.f, 0.f, 0.f, 0.f);
}

// ---------------------------------------------------------------------------
extern "C" void kernel_launch(void* const* d_in, const int* in_sizes, int n_in,
                              void* d_out, int out_size)
{
    const float* pose = (const float*)d_in[0];
    const float* act  = (const float*)d_in[1];
    const float* W    = (const float*)d_in[2];
    // d_in[3] = num_iter (== 3 in this problem; hardcoded below)

    float* out     = (float*)d_out;
    float* out_ncv = out + OFS_NCV;
    float* out_act = out + OFS_ACT;
    float* out_qk  = out + OFS_QK;
    float* out_emb = out + OFS_EMB;

    // 1) votes
    votes_kernel<<<dim3(NIN, MD / 256), 256>>>(pose, W);
    // 2) ncv0 = votes.sum(n) / Nout
    ncv0_kernel<<<(B_ * MD) / 256, 256>>>();
    // 3) iteration 1: g_ncv0 -> g_ncv1
    zero_g_kernel<<<64, 256>>>(1);
    iter_kernel<false><<<dim3(B_, NBLK), 256>>>(0, nullptr, act, nullptr, nullptr);
    // 4) iteration 2: g_ncv1 -> g_ncv0
    zero_g_kernel<<<64, 256>>>(0);
    iter_kernel<false><<<dim3(B_, NBLK), 256>>>(1, nullptr, act, nullptr, nullptr);
    // 5) iteration 3 (last): g_ncv0 -> d_out ncv; also qk + route_class_emb
    zero_ptr_kernel<<<64, 256>>>(out_ncv);
    iter_kernel<true><<<dim3(B_, NBLK), 256>>>(0, out_ncv, act, out_qk, out_emb);
    // 6) next_act = ||ncv||
    act_kernel<<<128, 256>>>(out_ncv, out_act);
}

// round 5
// speedup vs baseline: 1.1383x; 1.1356x over previous
#include <cuda_runtime.h>

// Problem constants (fixed by setup_inputs)
#define B_    32
#define NIN   512
#define DIN   64
#define NOUT  32
#define DOUT  64
#define MD    2048            // NOUT*DOUT
#define NCHUNK 32             // n per routing block
#define NBLK  (NIN / NCHUNK)  // 16
#define NGRP  8               // n per votes block (hierarchical ncv0 reduction)

// Output layout (concatenated, reference return order)
#define OFS_NCV 0
#define OFS_ACT (B_ * NOUT * DOUT)                 // 65536
#define OFS_QK  (OFS_ACT + B_ * NOUT)              // 66560
#define OFS_EMB (OFS_QK + B_ * NIN * NOUT)         // 590848

// Scratch (device globals; allocation-free rule)
__device__ float g_votes[(size_t)B_ * NIN * MD];   // 134 MB
__device__ float g_ncv0[B_ * MD];
__device__ float g_ncv1[B_ * MD];

// ---------------------------------------------------------------------------
// Votes: votes[b,n,m,d] = sum_a pose[b,n,a] * W[n,a,m,d]
// Block = (group of 8 n, 256-col chunk). 256 threads; each thread owns one
// column, all 32 batches as 16 packed f32x2 accumulators, plus a packed
// running n-sum that is atomically folded into g_ncv0 at the end (fused
// ncv0 = votes.sum(n)/Nout -> saves a full 134 MB re-read pass).
// W loads are double-buffered (4-ahead) to hide DRAM latency.
// ---------------------------------------------------------------------------
__global__ __launch_bounds__(256) void votes_kernel(
    const float* __restrict__ pose, const float* __restrict__ W)
{
    __shared__ float pose_t[DIN * B_];  // [a][b], b contiguous
    const int ng  = blockIdx.x;                       // 0..63
    const int col = blockIdx.y * 256 + threadIdx.x;   // 0..2047

    unsigned long long nacc[16];
#pragma unroll
    for (int p = 0; p < 16; p++) nacc[p] = 0ull;

    for (int i = 0; i < NGRP; i++) {
        const int n = ng * NGRP + i;

        __syncthreads();  // protect pose_t from previous n
        for (int idx = threadIdx.x; idx < B_ * DIN; idx += 256) {
            int b = idx >> 6, a = idx & 63;
            pose_t[a * B_ + b] = pose[((size_t)b * NIN + n) * DIN + a];
        }
        __syncthreads();

        unsigned long long acc[16];
#pragma unroll
        for (int p = 0; p < 16; p++) acc[p] = 0ull;

        const float* Wp = W + ((size_t)n * DIN) * MD + col;
        const ulonglong2* ps = reinterpret_cast<const ulonglong2*>(pose_t);

        float w[4];
#pragma unroll
        for (int u = 0; u < 4; u++) w[u] = Wp[(size_t)u * MD];

        for (int a = 0; a < DIN; a += 4) {
            float wn[4];
            if (a + 4 < DIN) {
#pragma unroll
                for (int u = 0; u < 4; u++) wn[u] = Wp[(size_t)(a + 4 + u) * MD];
            }
#pragma unroll
            for (int u = 0; u < 4; u++) {
                unsigned long long wp;
                asm("mov.b64 %0, {%1, %1};" : "=l"(wp) : "f"(w[u]));
#pragma unroll
                for (int j = 0; j < 8; j++) {
                    ulonglong2 q = ps[(a + u) * 8 + j];  // batches 4j..4j+3, row a+u
                    asm("fma.rn.f32x2 %0, %1, %2, %0;" : "+l"(acc[2 * j])     : "l"(q.x), "l"(wp));
                    asm("fma.rn.f32x2 %0, %1, %2, %0;" : "+l"(acc[2 * j + 1]) : "l"(q.y), "l"(wp));
                }
            }
#pragma unroll
            for (int u = 0; u < 4; u++) w[u] = wn[u];
        }

        float* vp = g_votes + (size_t)n * MD + col;
#pragma unroll
        for (int p = 0; p < 16; p++) {
            float lo, hi;
            asm("mov.b64 {%0, %1}, %2;" : "=f"(lo), "=f"(hi) : "l"(acc[p]));
            vp[(size_t)(2 * p)     * NIN * MD] = lo;
            vp[(size_t)(2 * p + 1) * NIN * MD] = hi;
            asm("add.rn.f32x2 %0, %0, %1;" : "+l"(nacc[p]) : "l"(acc[p]));
        }
    }

    // fold this block's n-partials into ncv0 (64 updates per address total)
#pragma unroll
    for (int p = 0; p < 16; p++) {
        float lo, hi;
        asm("mov.b64 {%0, %1}, %2;" : "=f"(lo), "=f"(hi) : "l"(nacc[p]));
        atomicAdd(&g_ncv0[(2 * p)     * MD + col], lo * (1.0f / NOUT));
        atomicAdd(&g_ncv0[(2 * p + 1) * MD + col], hi * (1.0f / NOUT));
    }
}

// ---------------------------------------------------------------------------
// One routing iteration, fully register-resident: votes staged 4 n's at a
// time in registers (no smem tile), ncv slice held in registers for the
// whole block, softmax batched over 4 n's across warps 0..3.
// 2 syncthreads per 4-n group. Last iteration also emits qk + emb.
// ---------------------------------------------------------------------------
template <bool LAST>
__global__ __launch_bounds__(256) void iter_kernel(
    int cur_sel, float* __restrict__ nxt_ext,
    const float* __restrict__ act,
    float* __restrict__ qk_out, float* __restrict__ emb_out)
{
    __shared__ float logits_s[4][NOUT];
    __shared__ float qa_s[4][NOUT];

    const float* cur = cur_sel ? g_ncv1 : g_ncv0;
    float* nxt = LAST ? nxt_ext : (cur_sel ? g_ncv0 : g_ncv1);

    const int b  = blockIdx.x;
    const int nc = blockIdx.y;
    const int t  = threadIdx.x;
    const int mcls = t >> 3;  // class owned by this thread's 8 md elements

    // ncv slice for this thread's md range (fixed for the whole block)
    float ncv_r[8];
    {
        const float4* c4 = reinterpret_cast<const float4*>(cur + b * MD + 8 * t);
        float4 c0 = c4[0], c1 = c4[1];
        ncv_r[0] = c0.x; ncv_r[1] = c0.y; ncv_r[2] = c0.z; ncv_r[3] = c0.w;
        ncv_r[4] = c1.x; ncv_r[5] = c1.y; ncv_r[6] = c1.z; ncv_r[7] = c1.w;
    }

    float acc[8];
#pragma unroll
    for (int k = 0; k < 8; k++) acc[k] = 0.f;

    const float* vbase = g_votes + ((size_t)b * NIN + (size_t)nc * NCHUNK) * MD + 8 * t;

    for (int g = 0; g < 8; g++) {
        // stage 4 n's of votes in registers (8 back-to-back LDG.128)
        float4 va[4][2];
#pragma unroll
        for (int j = 0; j < 4; j++) {
            const float4* p = reinterpret_cast<const float4*>(vbase + (size_t)(g * 4 + j) * MD);
            va[j][0] = p[0];
            va[j][1] = p[1];
        }

        // logits: dot over d, reduced across the 8 lanes covering class mcls
#pragma unroll
        for (int j = 0; j < 4; j++) {
            float p = va[j][0].x * ncv_r[0] + va[j][0].y * ncv_r[1]
                    + va[j][0].z * ncv_r[2] + va[j][0].w * ncv_r[3]
                    + va[j][1].x * ncv_r[4] + va[j][1].y * ncv_r[5]
                    + va[j][1].z * ncv_r[6] + va[j][1].w * ncv_r[7];
            p += __shfl_xor_sync(0xffffffffu, p, 4);
            p += __shfl_xor_sync(0xffffffffu, p, 2);
            p += __shfl_xor_sync(0xffffffffu, p, 1);
            if ((t & 7) == 0) logits_s[j][mcls] = p;
        }
        __syncthreads();

        // softmax over 32 classes for 4 n's in parallel (warps 0..3)
        if (t < 128) {
            const int j = t >> 5, m = t & 31;
            const int n = nc * NCHUNK + g * 4 + j;
            float x = logits_s[j][m] * 0.125f;  // 1/sqrt(Dout)
            float mx = x;
#pragma unroll
            for (int o = 16; o > 0; o >>= 1) mx = fmaxf(mx, __shfl_xor_sync(0xffffffffu, mx, o));
            float e = __expf(x - mx);
            float s = e;
#pragma unroll
            for (int o = 16; o > 0; o >>= 1) s += __shfl_xor_sync(0xffffffffu, s, o);
            float qk = e / s;
            qa_s[j][m] = qk * __ldg(&act[b * NIN + n]);
            if (LAST) qk_out[(size_t)(b * NIN + n) * NOUT + m] = qk;
        }
        __syncthreads();

        // weighted aggregation from registers; last iter emits emb
#pragma unroll
        for (int j = 0; j < 4; j++) {
            const float qa = qa_s[j][mcls];
            float v0 = va[j][0].x * qa, v1 = va[j][0].y * qa;
            float v2 = va[j][0].z * qa, v3 = va[j][0].w * qa;
            float v4 = va[j][1].x * qa, v5 = va[j][1].y * qa;
            float v6 = va[j][1].z * qa, v7 = va[j][1].w * qa;
            acc[0] += v0; acc[1] += v1; acc[2] += v2; acc[3] += v3;
            acc[4] += v4; acc[5] += v5; acc[6] += v6; acc[7] += v7;
            if (LAST) {
                float* ep = emb_out
                    + ((size_t)(b * NIN + nc * NCHUNK + g * 4 + j)) * MD + 8 * t;
                reinterpret_cast<float4*>(ep)[0] = make_float4(v0, v1, v2, v3);
                reinterpret_cast<float4*>(ep)[1] = make_float4(v4, v5, v6, v7);
            }
        }
        // no 3rd sync needed: next group writes logits_s (distinct from qa_s),
        // and the pre-softmax barrier orders qa_s reads vs rewrites.
    }

    float* np = nxt + b * MD + 8 * t;
#pragma unroll
    for (int k = 0; k < 8; k++) atomicAdd(&np[k], acc[k]);
}

// ---------------------------------------------------------------------------
// next_act[b,m] = ||ncv[b,m,:]||_2  (one warp per output)
// ---------------------------------------------------------------------------
__global__ __launch_bounds__(256) void act_kernel(
    const float* __restrict__ ncv, float* __restrict__ out)
{
    int g = (blockIdx.x * 256 + threadIdx.x) >> 5;  // 0..1023
    int l = threadIdx.x & 31;
    float v0 = ncv[g * 64 + l];
    float v1 = ncv[g * 64 + 32 + l];
    float s = v0 * v0 + v1 * v1;
#pragma unroll
    for (int o = 16; o > 0; o >>= 1) s += __shfl_xor_sync(0xffffffffu, s, o);
    if (l == 0) out[g] = sqrtf(s);
}

// ---------------------------------------------------------------------------
__global__ void zero_both_kernel()
{
    int i = blockIdx.x * 256 + threadIdx.x;
    if (i < (B_ * MD) / 4) {
        reinterpret_cast<float4*>(g_ncv0)[i] = make_float4(0.f, 0.f, 0.f, 0.f);
        reinterpret_cast<float4*>(g_ncv1)[i] = make_float4(0.f, 0.f, 0.f, 0.f);
    }
}

__global__ void zero_g_kernel(int sel)
{
    float4* p = reinterpret_cast<float4*>(sel ? g_ncv1 : g_ncv0);
    int i = blockIdx.x * 256 + threadIdx.x;
    if (i < (B_ * MD) / 4) p[i] = make_float4(0.f, 0.f, 0.f, 0.f);
}

__global__ void zero_ptr_kernel(float* p)
{
    int i = blockIdx.x * 256 + threadIdx.x;
    if (i < (B_ * MD) / 4) reinterpret_cast<float4*>(p)[i] = make_float4(0.f, 0.f, 0.f, 0.f);
}

// ---------------------------------------------------------------------------
extern "C" void kernel_launch(void* const* d_in, const int* in_sizes, int n_in,
                              void* d_out, int out_size)
{
    const float* pose = (const float*)d_in[0];
    const float* act  = (const float*)d_in[1];
    const float* W    = (const float*)d_in[2];
    // d_in[3] = num_iter (== 3 in this problem; hardcoded below)

    float* out     = (float*)d_out;
    float* out_ncv = out + OFS_NCV;
    float* out_act = out + OFS_ACT;
    float* out_qk  = out + OFS_QK;
    float* out_emb = out + OFS_EMB;

    // 0) zero ncv0 (atomic target of votes) and ncv1 (target of iter1)
    zero_both_kernel<<<64, 256>>>();
    // 1) votes + fused ncv0 = votes.sum(n)/Nout
    votes_kernel<<<dim3(NIN / NGRP, MD / 256), 256>>>(pose, W);
    // 2) iteration 1: g_ncv0 -> g_ncv1
    iter_kernel<false><<<dim3(B_, NBLK), 256>>>(0, nullptr, act, nullptr, nullptr);
    // 3) iteration 2: g_ncv1 -> g_ncv0 (zero target first; iter1 no longer needs it)
    zero_g_kernel<<<64, 256>>>(0);
    iter_kernel<false><<<dim3(B_, NBLK), 256>>>(1, nullptr, act, nullptr, nullptr);
    // 4) iteration 3 (last): g_ncv0 -> d_out ncv; also qk + route_class_emb
    zero_ptr_kernel<<<64, 256>>>(out_ncv);
    iter_kernel<true><<<dim3(B_, NBLK), 256>>>(0, out_ncv, act, out_qk, out_emb);
    // 5) next_act = ||ncv||
    act_kernel<<<128, 256>>>(out_ncv, out_act);
}

// round 7
// speedup vs baseline: 1.1743x; 1.0316x over previous
#include <cuda_runtime.h>

// Problem constants (fixed by setup_inputs)
#define B_    32
#define NIN   512
#define DIN   64
#define NOUT  32
#define DOUT  64
#define MD    2048            // NOUT*DOUT
#define NCHUNK 32             // n per routing block
#define NBLK  (NIN / NCHUNK)  // 16
#define NGRP  8               // n per votes block (hierarchical ncv0 reduction)

// Output layout (concatenated, reference return order)
#define OFS_NCV 0
#define OFS_ACT (B_ * NOUT * DOUT)                 // 65536
#define OFS_QK  (OFS_ACT + B_ * NOUT)              // 66560
#define OFS_EMB (OFS_QK + B_ * NIN * NOUT)         // 590848

// Scratch (device globals; allocation-free rule)
__device__ float g_votes[(size_t)B_ * NIN * MD];   // 134 MB
__device__ float g_ncv0[B_ * MD];
__device__ float g_ncv1[B_ * MD];

// ---------------------------------------------------------------------------
// Votes: votes[b,n,m,d] = sum_a pose[b,n,a] * W[n,a,m,d]
// Block = (group of 8 n, 256-col chunk). Each thread owns one column, all 32
// batches as 16 packed f32x2 accumulators, plus a packed running n-sum folded
// atomically into g_ncv0 (fused ncv0 pass). W prefetched 8-deep (MLP 8) to
// cover DRAM latency at full bandwidth.
// ---------------------------------------------------------------------------
__global__ __launch_bounds__(256) void votes_kernel(
    const float* __restrict__ pose, const float* __restrict__ W)
{
    __shared__ float pose_t[DIN * B_];  // [a][b], b contiguous
    const int ng  = blockIdx.x;                       // 0..63
    const int col = blockIdx.y * 256 + threadIdx.x;   // 0..2047

    unsigned long long nacc[16];
#pragma unroll
    for (int p = 0; p < 16; p++) nacc[p] = 0ull;

    for (int i = 0; i < NGRP; i++) {
        const int n = ng * NGRP + i;

        __syncthreads();  // protect pose_t from previous n
        for (int idx = threadIdx.x; idx < B_ * DIN; idx += 256) {
            int b = idx >> 6, a = idx & 63;
            pose_t[a * B_ + b] = pose[((size_t)b * NIN + n) * DIN + a];
        }
        __syncthreads();

        unsigned long long acc[16];
#pragma unroll
        for (int p = 0; p < 16; p++) acc[p] = 0ull;

        const float* Wp = W + ((size_t)n * DIN) * MD + col;
        const ulonglong2* ps = reinterpret_cast<const ulonglong2*>(pose_t);

        float w[8];
#pragma unroll
        for (int u = 0; u < 8; u++) w[u] = Wp[(size_t)u * MD];

        for (int a = 0; a < DIN; a += 8) {
            float wn[8];
            if (a + 8 < DIN) {
#pragma unroll
                for (int u = 0; u < 8; u++) wn[u] = Wp[(size_t)(a + 8 + u) * MD];
            }
#pragma unroll
            for (int u = 0; u < 8; u++) {
                unsigned long long wp;
                asm("mov.b64 %0, {%1, %1};" : "=l"(wp) : "f"(w[u]));
#pragma unroll
                for (int j = 0; j < 8; j++) {
                    ulonglong2 q = ps[(a + u) * 8 + j];  // batches 4j..4j+3, row a+u
                    asm("fma.rn.f32x2 %0, %1, %2, %0;" : "+l"(acc[2 * j])     : "l"(q.x), "l"(wp));
                    asm("fma.rn.f32x2 %0, %1, %2, %0;" : "+l"(acc[2 * j + 1]) : "l"(q.y), "l"(wp));
                }
            }
#pragma unroll
            for (int u = 0; u < 8; u++) w[u] = wn[u];
        }

        float* vp = g_votes + (size_t)n * MD + col;
#pragma unroll
        for (int p = 0; p < 16; p++) {
            float lo, hi;
            asm("mov.b64 {%0, %1}, %2;" : "=f"(lo), "=f"(hi) : "l"(acc[p]));
            vp[(size_t)(2 * p)     * NIN * MD] = lo;
            vp[(size_t)(2 * p + 1) * NIN * MD] = hi;
            asm("add.rn.f32x2 %0, %0, %1;" : "+l"(nacc[p]) : "l"(acc[p]));
        }
    }

    // fold this block's n-partials into ncv0 (64 updates per address total)
#pragma unroll
    for (int p = 0; p < 16; p++) {
        float lo, hi;
        asm("mov.b64 {%0, %1}, %2;" : "=f"(lo), "=f"(hi) : "l"(nacc[p]));
        atomicAdd(&g_ncv0[(2 * p)     * MD + col], lo * (1.0f / NOUT));
        atomicAdd(&g_ncv0[(2 * p + 1) * MD + col], hi * (1.0f / NOUT));
    }
}

// ---------------------------------------------------------------------------
// One routing iteration. Software-pipelined: group g+1's votes (8 LDG.128)
// are prefetched before group g's compute, overlapping DRAM latency with
// logits/softmax/aggregation. ONE barrier per group: logits smem is parity
// double-buffered and softmax is computed redundantly in every warp
// (lane = class), each thread fetching its qa via a single shfl.
// Last iteration also emits qk + route_class_emb.
// ---------------------------------------------------------------------------
template <bool LAST>
__global__ __launch_bounds__(256) void iter_kernel(
    int cur_sel, float* __restrict__ nxt_ext,
    const float* __restrict__ act,
    float* __restrict__ qk_out, float* __restrict__ emb_out)
{
    __shared__ float logits_s[2][4][NOUT];  // parity double buffer

    const float* cur = cur_sel ? g_ncv1 : g_ncv0;
    float* nxt = LAST ? nxt_ext : (cur_sel ? g_ncv0 : g_ncv1);

    const int b  = blockIdx.x;
    const int nc = blockIdx.y;
    const int t  = threadIdx.x;
    const int w  = t >> 5, l = t & 31;
    const int mcls = t >> 3;          // class owned by this thread's 8 md elems
    const int qsrc = mcls;            // shfl source lane holding qa for mcls

    // ncv slice for this thread's md range (fixed for the whole block)
    float ncv_r[8];
    {
        const float4* c4 = reinterpret_cast<const float4*>(cur + b * MD + 8 * t);
        float4 c0 = c4[0], c1 = c4[1];
        ncv_r[0] = c0.x; ncv_r[1] = c0.y; ncv_r[2] = c0.z; ncv_r[3] = c0.w;
        ncv_r[4] = c1.x; ncv_r[5] = c1.y; ncv_r[6] = c1.z; ncv_r[7] = c1.w;
    }

    float acc[8];
#pragma unroll
    for (int k = 0; k < 8; k++) acc[k] = 0.f;

    const float* vbase = g_votes + ((size_t)b * NIN + (size_t)nc * NCHUNK) * MD + 8 * t;

    // prefetch group 0
    float4 va[4][2];
#pragma unroll
    for (int j = 0; j < 4; j++) {
        const float4* p = reinterpret_cast<const float4*>(vbase + (size_t)j * MD);
        va[j][0] = p[0];
        va[j][1] = p[1];
    }

#pragma unroll
    for (int g = 0; g < 8; g++) {
        // prefetch next group while computing this one
        float4 vb[4][2];
        if (g < 7) {
#pragma unroll
            for (int j = 0; j < 4; j++) {
                const float4* p =
                    reinterpret_cast<const float4*>(vbase + (size_t)((g + 1) * 4 + j) * MD);
                vb[j][0] = p[0];
                vb[j][1] = p[1];
            }
        }

        // logits: dot over d, reduced across the 8 lanes covering class mcls
#pragma unroll
        for (int j = 0; j < 4; j++) {
            float p = va[j][0].x * ncv_r[0] + va[j][0].y * ncv_r[1]
                    + va[j][0].z * ncv_r[2] + va[j][0].w * ncv_r[3]
                    + va[j][1].x * ncv_r[4] + va[j][1].y * ncv_r[5]
                    + va[j][1].z * ncv_r[6] + va[j][1].w * ncv_r[7];
            p += __shfl_xor_sync(0xffffffffu, p, 4);
            p += __shfl_xor_sync(0xffffffffu, p, 2);
            p += __shfl_xor_sync(0xffffffffu, p, 1);
            if ((t & 7) == 0) logits_s[g & 1][j][mcls] = p;
        }
        __syncthreads();  // the ONLY barrier per group

        // softmax over 32 classes, redundantly in every warp (lane l = class l)
        float qa[4];
#pragma unroll
        for (int j = 0; j < 4; j++) {
            const int n = nc * NCHUNK + g * 4 + j;
            float x = logits_s[g & 1][j][l] * 0.125f;  // 1/sqrt(Dout)
            float mx = x;
#pragma unroll
            for (int o = 16; o > 0; o >>= 1) mx = fmaxf(mx, __shfl_xor_sync(0xffffffffu, mx, o));
            float e = __expf(x - mx);
            float s = e;
#pragma unroll
            for (int o = 16; o > 0; o >>= 1) s += __shfl_xor_sync(0xffffffffu, s, o);
            float qk = e / s;
            if (LAST && w == 0) qk_out[(size_t)(b * NIN + n) * NOUT + l] = qk;
            float qav = qk * __ldg(&act[b * NIN + n]);
            qa[j] = __shfl_sync(0xffffffffu, qav, qsrc);
        }

        // weighted aggregation from registers; last iter emits emb
#pragma unroll
        for (int j = 0; j < 4; j++) {
            float v0 = va[j][0].x * qa[j], v1 = va[j][0].y * qa[j];
            float v2 = va[j][0].z * qa[j], v3 = va[j][0].w * qa[j];
            float v4 = va[j][1].x * qa[j], v5 = va[j][1].y * qa[j];
            float v6 = va[j][1].z * qa[j], v7 = va[j][1].w * qa[j];
            acc[0] += v0; acc[1] += v1; acc[2] += v2; acc[3] += v3;
            acc[4] += v4; acc[5] += v5; acc[6] += v6; acc[7] += v7;
            if (LAST) {
                float* ep = emb_out
                    + ((size_t)(b * NIN + nc * NCHUNK + g * 4 + j)) * MD + 8 * t;
                reinterpret_cast<float4*>(ep)[0] = make_float4(v0, v1, v2, v3);
                reinterpret_cast<float4*>(ep)[1] = make_float4(v4, v5, v6, v7);
            }
        }

        // rotate prefetch buffer
#pragma unroll
        for (int j = 0; j < 4; j++) {
            va[j][0] = vb[j][0];
            va[j][1] = vb[j][1];
        }
    }

    float* np = nxt + b * MD + 8 * t;
#pragma unroll
    for (int k = 0; k < 8; k++) atomicAdd(&np[k], acc[k]);
}

// ---------------------------------------------------------------------------
// next_act[b,m] = ||ncv[b,m,:]||_2  (one warp per output)
// ---------------------------------------------------------------------------
__global__ __launch_bounds__(256) void act_kernel(
    const float* __restrict__ ncv, float* __restrict__ out)
{
    int g = (blockIdx.x * 256 + threadIdx.x) >> 5;  // 0..1023
    int l = threadIdx.x & 31;
    float v0 = ncv[g * 64 + l];
    float v1 = ncv[g * 64 + 32 + l];
    float s = v0 * v0 + v1 * v1;
#pragma unroll
    for (int o = 16; o > 0; o >>= 1) s += __shfl_xor_sync(0xffffffffu, s, o);
    if (l == 0) out[g] = sqrtf(s);
}

// ---------------------------------------------------------------------------
// Zero all three atomic targets (ncv0, ncv1, out_ncv) in one launch.
// ---------------------------------------------------------------------------
__global__ void zero3_kernel(float* __restrict__ out_ncv)
{
    int i = blockIdx.x * 256 + threadIdx.x;
    if (i < (B_ * MD) / 4) {
        float4 z = make_float4(0.f, 0.f, 0.f, 0.f);
        reinterpret_cast<float4*>(g_ncv0)[i] = z;
        reinterpret_cast<float4*>(g_ncv1)[i] = z;
        reinterpret_cast<float4*>(out_ncv)[i] = z;
    }
}

__global__ void zero_g_kernel(int sel)
{
    float4* p = reinterpret_cast<float4*>(sel ? g_ncv1 : g_ncv0);
    int i = blockIdx.x * 256 + threadIdx.x;
    if (i < (B_ * MD) / 4) p[i] = make_float4(0.f, 0.f, 0.f, 0.f);
}

// ---------------------------------------------------------------------------
extern "C" void kernel_launch(void* const* d_in, const int* in_sizes, int n_in,
                              void* d_out, int out_size)
{
    const float* pose = (const float*)d_in[0];
    const float* act  = (const float*)d_in[1];
    const float* W    = (const float*)d_in[2];
    // d_in[3] = num_iter (== 3 in this problem; hardcoded below)

    float* out     = (float*)d_out;
    float* out_ncv = out + OFS_NCV;
    float* out_act = out + OFS_ACT;
    float* out_qk  = out + OFS_QK;
    float* out_emb = out + OFS_EMB;

    // 0) zero all atomic accumulation targets up front
    zero3_kernel<<<64, 256>>>(out_ncv);
    // 1) votes + fused ncv0 = votes.sum(n)/Nout
    votes_kernel<<<dim3(NIN / NGRP, MD / 256), 256>>>(pose, W);
    // 2) iteration 1: g_ncv0 -> g_ncv1
    iter_kernel<false><<<dim3(B_, NBLK), 256>>>(0, nullptr, act, nullptr, nullptr);
    // 3) iteration 2: g_ncv1 -> g_ncv0 (re-zero target; iter1 no longer needs it)
    zero_g_kernel<<<64, 256>>>(0);
    iter_kernel<false><<<dim3(B_, NBLK), 256>>>(1, nullptr, act, nullptr, nullptr);
    // 4) iteration 3 (last): g_ncv0 -> d_out ncv; also qk + route_class_emb
    iter_kernel<true><<<dim3(B_, NBLK), 256>>>(0, out_ncv, act, out_qk, out_emb);
    // 5) next_act = ||ncv||
    act_kernel<<<128, 256>>>(out_ncv, out_act);
}